// round 2
// baseline (speedup 1.0000x reference)
#include <cuda_runtime.h>
#include <math.h>

// ---------------- problem constants ----------------
#define BATCH 64
#define HS_   56
#define CC    128
#define NWH_  8
#define NW_   64
#define NH_   4
#define DH_   32
#define NN_   49
#define HID_  512
#define PIX   (BATCH*HS_*HS_)      // 200704
#define M1_   PIX                  // window-token rows
#define M2_   (BATCH*28*28)        // 50176 merged rows

// ---------------- scratch (static device memory; allocation-free) ----------
__device__ float g_hw[(size_t)M1_*CC];       // LN1+windowed activations; reused for LN2 output
__device__ float g_qkv[(size_t)M1_*3*CC];    // qkv projections
__device__ float g_o[(size_t)M1_*CC];        // attention output; reused as merged xm (M2*512 == M1*128)
__device__ float g_xres[(size_t)M1_*CC];     // residual stream (pixel layout B,H,W,C)
__device__ float g_fc1[(size_t)M1_*HID_];    // fc1+gelu output

// ---------------- LN1 + roll(-3,-3) + window partition ----------------
// 1 warp per OUTPUT pixel. out row = (b*64 + wi*8+wj)*49 + pi*7+pj
__global__ void ln1_win_kernel(const float* __restrict__ x,
                               const float* __restrict__ gw,
                               const float* __restrict__ gb)
{
    int warp = (blockIdx.x * blockDim.x + threadIdx.x) >> 5;
    int lane = threadIdx.x & 31;
    int b   = warp / 3136;
    int rem = warp - b * 3136;
    int i = rem / 56;
    int j = rem - i * 56;
    int si = i + 3; if (si >= 56) si -= 56;
    int sj = j + 3; if (sj >= 56) sj -= 56;
    float4 v = *(const float4*)(x + ((((size_t)b*56 + si)*56) + sj)*128 + lane*4);
    float s  = v.x + v.y + v.z + v.w;
    float ss = v.x*v.x + v.y*v.y + v.z*v.z + v.w*v.w;
    #pragma unroll
    for (int o = 16; o; o >>= 1) {
        s  += __shfl_xor_sync(0xffffffffu, s,  o);
        ss += __shfl_xor_sync(0xffffffffu, ss, o);
    }
    float mean = s * (1.0f/128.0f);
    float var  = ss * (1.0f/128.0f) - mean*mean;
    float rstd = rsqrtf(var + 1e-5f);
    float4 wv = *(const float4*)(gw + lane*4);
    float4 bv = *(const float4*)(gb + lane*4);
    float4 o4;
    o4.x = (v.x - mean)*rstd*wv.x + bv.x;
    o4.y = (v.y - mean)*rstd*wv.y + bv.y;
    o4.z = (v.z - mean)*rstd*wv.z + bv.z;
    o4.w = (v.w - mean)*rstd*wv.w + bv.w;
    int i7 = i / 7, j7 = j / 7;
    int widx = i7*8 + j7;
    int n    = (i - i7*7)*7 + (j - j7*7);
    size_t row = (size_t)(b*64 + widx)*49 + n;
    *(float4*)(g_hw + row*128 + lane*4) = o4;
}

// ---------------- LN2 (pixel layout, identity mapping): g_xres -> g_hw ----
__global__ void ln2_kernel(const float* __restrict__ gw, const float* __restrict__ gb)
{
    int warp = (blockIdx.x * blockDim.x + threadIdx.x) >> 5;
    int lane = threadIdx.x & 31;
    float4 v = *(const float4*)(g_xres + (size_t)warp*128 + lane*4);
    float s  = v.x + v.y + v.z + v.w;
    float ss = v.x*v.x + v.y*v.y + v.z*v.z + v.w*v.w;
    #pragma unroll
    for (int o = 16; o; o >>= 1) {
        s  += __shfl_xor_sync(0xffffffffu, s,  o);
        ss += __shfl_xor_sync(0xffffffffu, ss, o);
    }
    float mean = s * (1.0f/128.0f);
    float var  = ss * (1.0f/128.0f) - mean*mean;
    float rstd = rsqrtf(var + 1e-5f);
    float4 wv = *(const float4*)(gw + lane*4);
    float4 bv = *(const float4*)(gb + lane*4);
    float4 o4;
    o4.x = (v.x - mean)*rstd*wv.x + bv.x;
    o4.y = (v.y - mean)*rstd*wv.y + bv.y;
    o4.z = (v.z - mean)*rstd*wv.z + bv.z;
    o4.w = (v.w - mean)*rstd*wv.w + bv.w;
    *(float4*)(g_hw + (size_t)warp*128 + lane*4) = o4;
}

// ---------------- patch-merge gather + LN(512): g_xres -> g_o(as xm) -----
__global__ void merge_ln_kernel(const float* __restrict__ gw, const float* __restrict__ gb)
{
    int warp = (blockIdx.x * blockDim.x + threadIdx.x) >> 5;
    int lane = threadIdx.x & 31;
    int b   = warp / 784;
    int rem = warp - b * 784;
    int i2 = rem / 28;
    int j2 = rem - i2 * 28;
    int i0 = 2*i2, j0 = 2*j2;
    const float* p0 = g_xres + (((size_t)b*56 + i0    )*56 + j0    )*128;
    const float* p1 = g_xres + (((size_t)b*56 + i0 + 1)*56 + j0    )*128;
    const float* p2 = g_xres + (((size_t)b*56 + i0    )*56 + j0 + 1)*128;
    const float* p3 = g_xres + (((size_t)b*56 + i0 + 1)*56 + j0 + 1)*128;
    float4 v[4];
    v[0] = *(const float4*)(p0 + lane*4);
    v[1] = *(const float4*)(p1 + lane*4);
    v[2] = *(const float4*)(p2 + lane*4);
    v[3] = *(const float4*)(p3 + lane*4);
    float s = 0.f, ss = 0.f;
    #pragma unroll
    for (int q = 0; q < 4; q++) {
        s  += v[q].x + v[q].y + v[q].z + v[q].w;
        ss += v[q].x*v[q].x + v[q].y*v[q].y + v[q].z*v[q].z + v[q].w*v[q].w;
    }
    #pragma unroll
    for (int o = 16; o; o >>= 1) {
        s  += __shfl_xor_sync(0xffffffffu, s,  o);
        ss += __shfl_xor_sync(0xffffffffu, ss, o);
    }
    float mean = s * (1.0f/512.0f);
    float var  = ss * (1.0f/512.0f) - mean*mean;
    float rstd = rsqrtf(var + 1e-5f);
    float* out = g_o + (size_t)warp*512;
    #pragma unroll
    for (int q = 0; q < 4; q++) {
        int c = q*128 + lane*4;
        float4 wv = *(const float4*)(gw + c);
        float4 bv = *(const float4*)(gb + c);
        float4 o4;
        o4.x = (v[q].x - mean)*rstd*wv.x + bv.x;
        o4.y = (v[q].y - mean)*rstd*wv.y + bv.y;
        o4.z = (v[q].z - mean)*rstd*wv.z + bv.z;
        o4.w = (v[q].w - mean)*rstd*wv.w + bv.w;
        *(float4*)(out + c) = o4;
    }
}

// ---------------- attention: one 64-thread block per (window, head) -------
__global__ __launch_bounds__(64) void attn_kernel(
    const float* __restrict__ qkv, const float* __restrict__ rpb,
    const int* __restrict__ rel_index, const float* __restrict__ mask,
    float* __restrict__ outp)
{
    int win = blockIdx.x;
    int h   = blockIdx.y;
    __shared__ float qs[49][33];   // padded: row-major register fill without 49-way conflicts
    __shared__ float ks[49][32];
    __shared__ float vs[49][32];
    int t = threadIdx.x;
    for (int idx = t; idx < 49*32; idx += 64) {
        int n = idx >> 5, d = idx & 31;
        const float* base = qkv + ((size_t)(win*49 + n))*384 + h*32 + d;
        qs[n][d] = base[0];
        ks[n][d] = base[128];
        vs[n][d] = base[256];
    }
    __syncthreads();
    if (t < 49) {
        float qr[32];
        #pragma unroll
        for (int d = 0; d < 32; d++) qr[d] = qs[t][d];
        int wimg = win & 63;
        const float* mrow = mask + ((size_t)(wimg*49 + t))*49;
        const int*   rrow = rel_index + t*49;
        float s[49];
        float mx = -1e30f;
        #pragma unroll
        for (int m = 0; m < 49; m++) {
            float acc = 0.f;
            #pragma unroll
            for (int d = 0; d < 32; d++) acc += qr[d] * ks[m][d];
            acc += rpb[rrow[m]*4 + h] + mrow[m];
            s[m] = acc;
            mx = fmaxf(mx, acc);
        }
        float sum = 0.f;
        #pragma unroll
        for (int m = 0; m < 49; m++) { s[m] = __expf(s[m] - mx); sum += s[m]; }
        float inv = 1.f / sum;
        float* orow = outp + ((size_t)(win*49 + t))*128 + h*32;
        #pragma unroll
        for (int d = 0; d < 32; d++) {
            float acc = 0.f;
            #pragma unroll
            for (int m = 0; m < 49; m++) acc += s[m] * vs[m][d];
            orow[d] = acc * inv;
        }
    }
}

// ---------------- SGEMM 128x64 tile: C[M,Nd] = A[M,K] @ W[Nd,K]^T + epi ---
// EPI 0: (+bias if non-null) plain store
// EPI 1: +bias; cols<128 (q) scaled by 1/sqrt(32)
// EPI 2: +bias; window-reverse + roll(+3,+3) scatter; + residual aux (input x)
// EPI 3: +bias; exact GELU
// EPI 4: +bias; + residual aux (in-place on g_xres)
template<int EPI>
__global__ __launch_bounds__(256) void sgemm_kernel(
    const float* __restrict__ A, const float* __restrict__ W,
    const float* __restrict__ bias, float* __restrict__ C,
    const float* __restrict__ aux, int M, int Nd, int K)
{
    __shared__ __align__(16) float As[32][128];
    __shared__ __align__(16) float Bs[32][64];
    const int t  = threadIdx.x;
    const int tx = t & 15;          // 16 col-groups of 4  -> 64 cols
    const int ty = t >> 4;          // 16 row-groups of 8  -> 128 rows
    const int bm = blockIdx.y * 128;
    const int bn = blockIdx.x * 64;
    const int row0 = t >> 3;        // 0..31
    const int c4   = t & 7;         // k-chunk of 4
    float acc[8][4] = {};
    for (int k0 = 0; k0 < K; k0 += 32) {
        #pragma unroll
        for (int l = 0; l < 4; l++) {               // A: 128 rows
            int row = row0 + l*32;
            float4 a = *(const float4*)(A + (size_t)(bm + row)*K + k0 + c4*4);
            As[c4*4+0][row] = a.x;  As[c4*4+1][row] = a.y;
            As[c4*4+2][row] = a.z;  As[c4*4+3][row] = a.w;
        }
        #pragma unroll
        for (int l = 0; l < 2; l++) {               // W: 64 rows
            int row = row0 + l*32;
            float4 w4 = *(const float4*)(W + (size_t)(bn + row)*K + k0 + c4*4);
            Bs[c4*4+0][row] = w4.x; Bs[c4*4+1][row] = w4.y;
            Bs[c4*4+2][row] = w4.z; Bs[c4*4+3][row] = w4.w;
        }
        __syncthreads();
        #pragma unroll
        for (int k = 0; k < 32; k++) {
            float4 a0 = *(const float4*)&As[k][ty*8];
            float4 a1 = *(const float4*)&As[k][ty*8 + 4];
            float4 bf = *(const float4*)&Bs[k][tx*4];
            float ar[8] = {a0.x, a0.y, a0.z, a0.w, a1.x, a1.y, a1.z, a1.w};
            float br[4] = {bf.x, bf.y, bf.z, bf.w};
            #pragma unroll
            for (int i = 0; i < 8; i++)
                #pragma unroll
                for (int j = 0; j < 4; j++)
                    acc[i][j] += ar[i] * br[j];
        }
        __syncthreads();
    }
    #pragma unroll
    for (int i = 0; i < 8; i++) {
        const int m = bm + ty*8 + i;
        size_t obase;
        if (EPI == 2) {
            int win = m / 49, nn = m - win*49;
            int bb = win >> 6, w = win & 63;
            int n7 = nn / 7;
            int pi = (w >> 3)*7 + n7;
            int pj = (w & 7)*7 + (nn - n7*7);
            int ii = pi + 3; if (ii >= 56) ii -= 56;
            int jj = pj + 3; if (jj >= 56) jj -= 56;
            obase = (((size_t)bb*56 + ii)*56 + jj)*128;
        } else {
            obase = (size_t)m * Nd;
        }
        #pragma unroll
        for (int j = 0; j < 4; j++) {
            const int n = bn + tx*4 + j;
            float v = acc[i][j];
            if (EPI == 0) {
                if (bias) v += bias[n];
                C[obase + n] = v;
            } else if (EPI == 1) {
                v += bias[n];
                if (n < 128) v *= 0.17677669529663687f;   // 1/sqrt(32)
                C[obase + n] = v;
            } else if (EPI == 2) {
                v += bias[n];
                C[obase + n] = v + aux[obase + n];
            } else if (EPI == 3) {
                v += bias[n];
                C[obase + n] = 0.5f * v * (1.0f + erff(v * 0.70710678118654752f));
            } else { // EPI == 4
                v += bias[n];
                C[obase + n] = v + aux[obase + n];
            }
        }
    }
}

// ---------------- launcher ----------------
extern "C" void kernel_launch(void* const* d_in, const int* in_sizes, int n_in,
                              void* d_out, int out_size)
{
    const float* x       = (const float*)d_in[0];
    const float* n1w     = (const float*)d_in[1];
    const float* n1b     = (const float*)d_in[2];
    const float* qkv_w   = (const float*)d_in[3];
    const float* qkv_b   = (const float*)d_in[4];
    const float* proj_w  = (const float*)d_in[5];
    const float* proj_b  = (const float*)d_in[6];
    const float* rpb     = (const float*)d_in[7];
    const float* n2w     = (const float*)d_in[8];
    const float* n2b     = (const float*)d_in[9];
    const float* fc1_w   = (const float*)d_in[10];
    const float* fc1_b   = (const float*)d_in[11];
    const float* fc2_w   = (const float*)d_in[12];
    const float* fc2_b   = (const float*)d_in[13];
    const float* mnw     = (const float*)d_in[14];
    const float* mnb     = (const float*)d_in[15];
    const float* merge_w = (const float*)d_in[16];
    const int*   rel_idx = (const int*)d_in[17];
    const float* amask   = (const float*)d_in[18];
    float* out = (float*)d_out;

    float *hw, *qkv, *o, *xres, *fc1;
    cudaGetSymbolAddress((void**)&hw,   g_hw);
    cudaGetSymbolAddress((void**)&qkv,  g_qkv);
    cudaGetSymbolAddress((void**)&o,    g_o);
    cudaGetSymbolAddress((void**)&xres, g_xres);
    cudaGetSymbolAddress((void**)&fc1,  g_fc1);

    // 1. LN1 + roll + window partition
    ln1_win_kernel<<<PIX/8, 256>>>(x, n1w, n1b);
    // 2. qkv GEMM (scale folded into q)
    sgemm_kernel<1><<<dim3(384/64, M1_/128), 256>>>(hw, qkv_w, qkv_b, qkv, nullptr, M1_, 384, 128);
    // 3. windowed attention
    attn_kernel<<<dim3(4096, NH_), 64>>>(qkv, rpb, rel_idx, amask, o);
    // 4. proj GEMM + window-reverse + roll-back + residual -> xres (pixel layout)
    sgemm_kernel<2><<<dim3(128/64, M1_/128), 256>>>(o, proj_w, proj_b, xres, x, M1_, 128, 128);
    // 5. LN2: xres -> g_hw (reuse)
    ln2_kernel<<<PIX/8, 256>>>(n2w, n2b);
    // 6. fc1 GEMM + GELU
    sgemm_kernel<3><<<dim3(512/64, M1_/128), 256>>>(hw, fc1_w, fc1_b, fc1, nullptr, M1_, 512, 128);
    // 7. fc2 GEMM + residual (in place on xres)
    sgemm_kernel<4><<<dim3(128/64, M1_/128), 256>>>(fc1, fc2_w, fc2_b, xres, xres, M1_, 128, 512);
    // 8. patch-merge gather + LN(512): xres -> g_o (reuse as xm)
    merge_ln_kernel<<<M2_/8, 256>>>(mnw, mnb);
    // 9. merge GEMM -> output
    sgemm_kernel<0><<<dim3(256/64, M2_/128), 256>>>(o, merge_w, nullptr, out, nullptr, M2_, 256, 512);
}

// round 4
// speedup vs baseline: 1.9279x; 1.9279x over previous
#include <cuda_runtime.h>
#include <math.h>
#include <stdint.h>

// ---------------- problem constants ----------------
#define BATCH 64
#define HS_   56
#define CC    128
#define NH_   4
#define HID_  512
#define PIX   (BATCH*HS_*HS_)      // 200704
#define M1_   PIX                  // window-token rows
#define M2_   (BATCH*28*28)        // 50176 merged rows

// ---------------- scratch (static device memory; allocation-free) ----------
__device__ float g_hw[(size_t)M1_*CC];       // LN1+windowed activations; reused for LN2 output
__device__ float g_qkv[(size_t)M1_*3*CC];    // qkv projections
__device__ float g_o[(size_t)M1_*CC];        // attention output; reused as merged xm
__device__ float g_xres[(size_t)M1_*CC];     // residual stream (pixel layout B,H,W,C)
__device__ float g_fc1[(size_t)M1_*HID_];    // fc1+gelu output

// ---------------- helpers ----------------
__device__ __forceinline__ uint32_t f2tf32(float x) {
    uint32_t r; asm("cvt.rna.tf32.f32 %0, %1;" : "=r"(r) : "f"(x)); return r;
}
__device__ __forceinline__ void mma_tf32(float* c, const uint32_t* a, uint32_t b0, uint32_t b1) {
    asm volatile("mma.sync.aligned.m16n8k8.row.col.f32.tf32.tf32.f32 "
        "{%0,%1,%2,%3}, {%4,%5,%6,%7}, {%8,%9}, {%0,%1,%2,%3};\n"
        : "+f"(c[0]), "+f"(c[1]), "+f"(c[2]), "+f"(c[3])
        : "r"(a[0]), "r"(a[1]), "r"(a[2]), "r"(a[3]), "r"(b0), "r"(b1));
}

// ---------------- LN1 + roll(-3,-3) + window partition ----------------
__global__ void ln1_win_kernel(const float* __restrict__ x,
                               const float* __restrict__ gw,
                               const float* __restrict__ gb)
{
    int warp = (blockIdx.x * blockDim.x + threadIdx.x) >> 5;
    int lane = threadIdx.x & 31;
    int b   = warp / 3136;
    int rem = warp - b * 3136;
    int i = rem / 56;
    int j = rem - i * 56;
    int si = i + 3; if (si >= 56) si -= 56;
    int sj = j + 3; if (sj >= 56) sj -= 56;
    float4 v = *(const float4*)(x + ((((size_t)b*56 + si)*56) + sj)*128 + lane*4);
    float s  = v.x + v.y + v.z + v.w;
    float ss = v.x*v.x + v.y*v.y + v.z*v.z + v.w*v.w;
    #pragma unroll
    for (int o = 16; o; o >>= 1) {
        s  += __shfl_xor_sync(0xffffffffu, s,  o);
        ss += __shfl_xor_sync(0xffffffffu, ss, o);
    }
    float mean = s * (1.0f/128.0f);
    float var  = ss * (1.0f/128.0f) - mean*mean;
    float rstd = rsqrtf(var + 1e-5f);
    float4 wv = *(const float4*)(gw + lane*4);
    float4 bv = *(const float4*)(gb + lane*4);
    float4 o4;
    o4.x = (v.x - mean)*rstd*wv.x + bv.x;
    o4.y = (v.y - mean)*rstd*wv.y + bv.y;
    o4.z = (v.z - mean)*rstd*wv.z + bv.z;
    o4.w = (v.w - mean)*rstd*wv.w + bv.w;
    int i7 = i / 7, j7 = j / 7;
    int widx = i7*8 + j7;
    int n    = (i - i7*7)*7 + (j - j7*7);
    size_t row = (size_t)(b*64 + widx)*49 + n;
    *(float4*)(g_hw + row*128 + lane*4) = o4;
}

// ---------------- LN2 (pixel layout, identity mapping): g_xres -> g_hw ----
__global__ void ln2_kernel(const float* __restrict__ gw, const float* __restrict__ gb)
{
    int warp = (blockIdx.x * blockDim.x + threadIdx.x) >> 5;
    int lane = threadIdx.x & 31;
    float4 v = *(const float4*)(g_xres + (size_t)warp*128 + lane*4);
    float s  = v.x + v.y + v.z + v.w;
    float ss = v.x*v.x + v.y*v.y + v.z*v.z + v.w*v.w;
    #pragma unroll
    for (int o = 16; o; o >>= 1) {
        s  += __shfl_xor_sync(0xffffffffu, s,  o);
        ss += __shfl_xor_sync(0xffffffffu, ss, o);
    }
    float mean = s * (1.0f/128.0f);
    float var  = ss * (1.0f/128.0f) - mean*mean;
    float rstd = rsqrtf(var + 1e-5f);
    float4 wv = *(const float4*)(gw + lane*4);
    float4 bv = *(const float4*)(gb + lane*4);
    float4 o4;
    o4.x = (v.x - mean)*rstd*wv.x + bv.x;
    o4.y = (v.y - mean)*rstd*wv.y + bv.y;
    o4.z = (v.z - mean)*rstd*wv.z + bv.z;
    o4.w = (v.w - mean)*rstd*wv.w + bv.w;
    *(float4*)(g_hw + (size_t)warp*128 + lane*4) = o4;
}

// ---------------- patch-merge gather + LN(512): g_xres -> g_o(as xm) -----
__global__ void merge_ln_kernel(const float* __restrict__ gw, const float* __restrict__ gb)
{
    int warp = (blockIdx.x * blockDim.x + threadIdx.x) >> 5;
    int lane = threadIdx.x & 31;
    int b   = warp / 784;
    int rem = warp - b * 784;
    int i2 = rem / 28;
    int j2 = rem - i2 * 28;
    int i0 = 2*i2, j0 = 2*j2;
    const float* p0 = g_xres + (((size_t)b*56 + i0    )*56 + j0    )*128;
    const float* p1 = g_xres + (((size_t)b*56 + i0 + 1)*56 + j0    )*128;
    const float* p2 = g_xres + (((size_t)b*56 + i0    )*56 + j0 + 1)*128;
    const float* p3 = g_xres + (((size_t)b*56 + i0 + 1)*56 + j0 + 1)*128;
    float4 v[4];
    v[0] = *(const float4*)(p0 + lane*4);
    v[1] = *(const float4*)(p1 + lane*4);
    v[2] = *(const float4*)(p2 + lane*4);
    v[3] = *(const float4*)(p3 + lane*4);
    float s = 0.f, ss = 0.f;
    #pragma unroll
    for (int q = 0; q < 4; q++) {
        s  += v[q].x + v[q].y + v[q].z + v[q].w;
        ss += v[q].x*v[q].x + v[q].y*v[q].y + v[q].z*v[q].z + v[q].w*v[q].w;
    }
    #pragma unroll
    for (int o = 16; o; o >>= 1) {
        s  += __shfl_xor_sync(0xffffffffu, s,  o);
        ss += __shfl_xor_sync(0xffffffffu, ss, o);
    }
    float mean = s * (1.0f/512.0f);
    float var  = ss * (1.0f/512.0f) - mean*mean;
    float rstd = rsqrtf(var + 1e-5f);
    float* out = g_o + (size_t)warp*512;
    #pragma unroll
    for (int q = 0; q < 4; q++) {
        int c = q*128 + lane*4;
        float4 wv = *(const float4*)(gw + c);
        float4 bv = *(const float4*)(gb + c);
        float4 o4;
        o4.x = (v[q].x - mean)*rstd*wv.x + bv.x;
        o4.y = (v[q].y - mean)*rstd*wv.y + bv.y;
        o4.z = (v[q].z - mean)*rstd*wv.z + bv.z;
        o4.w = (v[q].w - mean)*rstd*wv.w + bv.w;
        *(float4*)(out + c) = o4;
    }
}

// ---------------- attention: one 64-thread block per (window, head) -------
__global__ __launch_bounds__(64) void attn_kernel(
    const float* __restrict__ qkv, const float* __restrict__ rpb,
    const int* __restrict__ rel_index, const float* __restrict__ mask,
    float* __restrict__ outp)
{
    int win = blockIdx.x;
    int h   = blockIdx.y;
    __shared__ float qs[49][33];
    __shared__ float ks[49][32];
    __shared__ float vs[49][32];
    int t = threadIdx.x;
    for (int idx = t; idx < 49*32; idx += 64) {
        int n = idx >> 5, d = idx & 31;
        const float* base = qkv + ((size_t)(win*49 + n))*384 + h*32 + d;
        qs[n][d] = base[0];
        ks[n][d] = base[128];
        vs[n][d] = base[256];
    }
    __syncthreads();
    if (t < 49) {
        float qr[32];
        #pragma unroll
        for (int d = 0; d < 32; d++) qr[d] = qs[t][d];
        int wimg = win & 63;
        const float* mrow = mask + ((size_t)(wimg*49 + t))*49;
        const int*   rrow = rel_index + t*49;
        float s[49];
        float mx = -1e30f;
        #pragma unroll
        for (int m = 0; m < 49; m++) {
            float acc = 0.f;
            #pragma unroll
            for (int d = 0; d < 32; d++) acc += qr[d] * ks[m][d];
            acc += rpb[rrow[m]*4 + h] + mrow[m];
            s[m] = acc;
            mx = fmaxf(mx, acc);
        }
        float sum = 0.f;
        #pragma unroll
        for (int m = 0; m < 49; m++) { s[m] = __expf(s[m] - mx); sum += s[m]; }
        float inv = 1.f / sum;
        float* orow = outp + ((size_t)(win*49 + t))*128 + h*32;
        #pragma unroll
        for (int d = 0; d < 32; d++) {
            float acc = 0.f;
            #pragma unroll
            for (int m = 0; m < 49; m++) acc += s[m] * vs[m][d];
            orow[d] = acc * inv;
        }
    }
}

// ---------------- TF32 tensor-core GEMM: C[M,Nd] = A[M,K] @ W[Nd,K]^T + epi
// Block tile 128x64, BK=32, 8 warps (4m x 2n), warp tile 32x32 via m16n8k8.
// Register-prefetch pipeline: global loads for k-step s+1 issued before the
// mma block of k-step s.
// EPI 0: (+bias if non-null) plain store
// EPI 1: +bias; cols<128 (q) scaled by 1/sqrt(32)
// EPI 2: +bias; window-reverse + roll(+3,+3) scatter; + residual aux (input x)
// EPI 3: +bias; exact GELU
// EPI 4: +bias; + residual aux (in-place on g_xres)
template<int EPI>
__global__ __launch_bounds__(256) void tgemm_kernel(
    const float* __restrict__ A, const float* __restrict__ W,
    const float* __restrict__ bias, float* __restrict__ C,
    const float* __restrict__ aux, int M, int Nd, int K)
{
    __shared__ __align__(16) uint32_t As[128][36];   // [m][k], pad 36 -> conflict-free
    __shared__ __align__(16) uint32_t Bs[64][36];    // [n][k]
    const int t    = threadIdx.x;
    const int warp = t >> 5;
    const int lane = t & 31;
    const int qr   = lane >> 2;   // 0..7
    const int qc   = lane & 3;    // 0..3
    const int wm   = warp & 3;    // m warp 0..3
    const int wn   = warp >> 2;   // n warp 0..1
    const int bm   = blockIdx.y * 128;
    const int bn   = blockIdx.x * 64;
    const int row0 = t >> 3;      // 0..31
    const int c4   = t & 7;       // k chunk of 4

    const float* aptr = A + (size_t)(bm + row0)*K + c4*4;
    const float* wptr = W + (size_t)(bn + row0)*K + c4*4;
    const size_t astr = (size_t)32 * K;

    float acc[2][4][4] = {};      // [mfrag][nfrag][c0..c3]
    float4 a_reg[4], w_reg[2];

    // preload k-step 0
    #pragma unroll
    for (int l = 0; l < 4; l++) a_reg[l] = *(const float4*)(aptr + l*astr);
    #pragma unroll
    for (int l = 0; l < 2; l++) w_reg[l] = *(const float4*)(wptr + l*astr);

    for (int k0 = 0; k0 < K; k0 += 32) {
        // ---- stage current k-step into smem (tf32-converted) ----
        #pragma unroll
        for (int l = 0; l < 4; l++) {
            uint4 u;
            u.x = f2tf32(a_reg[l].x); u.y = f2tf32(a_reg[l].y);
            u.z = f2tf32(a_reg[l].z); u.w = f2tf32(a_reg[l].w);
            *(uint4*)&As[row0 + l*32][c4*4] = u;
        }
        #pragma unroll
        for (int l = 0; l < 2; l++) {
            uint4 u;
            u.x = f2tf32(w_reg[l].x); u.y = f2tf32(w_reg[l].y);
            u.z = f2tf32(w_reg[l].z); u.w = f2tf32(w_reg[l].w);
            *(uint4*)&Bs[row0 + l*32][c4*4] = u;
        }
        __syncthreads();
        // ---- prefetch next k-step into registers (overlaps with mma) ----
        if (k0 + 32 < K) {
            #pragma unroll
            for (int l = 0; l < 4; l++) a_reg[l] = *(const float4*)(aptr + (k0+32) + l*astr);
            #pragma unroll
            for (int l = 0; l < 2; l++) w_reg[l] = *(const float4*)(wptr + (k0+32) + l*astr);
        }
        // ---- 4 x m16n8k8 k-slices ----
        #pragma unroll
        for (int ks = 0; ks < 4; ks++) {
            const int kb = ks * 8;
            uint32_t af[2][4];
            #pragma unroll
            for (int i = 0; i < 2; i++) {
                int m0 = wm*32 + i*16 + qr;
                af[i][0] = As[m0    ][kb + qc    ];
                af[i][1] = As[m0 + 8][kb + qc    ];
                af[i][2] = As[m0    ][kb + qc + 4];
                af[i][3] = As[m0 + 8][kb + qc + 4];
            }
            #pragma unroll
            for (int j = 0; j < 4; j++) {
                int n0 = wn*32 + j*8 + qr;
                uint32_t b0 = Bs[n0][kb + qc    ];
                uint32_t b1 = Bs[n0][kb + qc + 4];
                #pragma unroll
                for (int i = 0; i < 2; i++)
                    mma_tf32(acc[i][j], af[i], b0, b1);
            }
        }
        __syncthreads();
    }

    // ---- epilogue ----
    #pragma unroll
    for (int i = 0; i < 2; i++) {
        #pragma unroll
        for (int half = 0; half < 2; half++) {
            const int m = bm + wm*32 + i*16 + qr + half*8;
            size_t obase;
            if (EPI == 2) {
                int win = m / 49, nn = m - win*49;
                int bb = win >> 6, w = win & 63;
                int n7 = nn / 7;
                int pi = (w >> 3)*7 + n7;
                int pj = (w & 7)*7 + (nn - n7*7);
                int ii = pi + 3; if (ii >= 56) ii -= 56;
                int jj = pj + 3; if (jj >= 56) jj -= 56;
                obase = (((size_t)bb*56 + ii)*56 + jj)*128;
            } else {
                obase = (size_t)m * Nd;
            }
            #pragma unroll
            for (int j = 0; j < 4; j++) {
                const int n = bn + wn*32 + j*8 + qc*2;
                #pragma unroll
                for (int e = 0; e < 2; e++) {
                    const int nc = n + e;
                    float v = acc[i][j][half*2 + e];
                    if (EPI == 0) {
                        if (bias) v += bias[nc];
                        C[obase + nc] = v;
                    } else if (EPI == 1) {
                        v += bias[nc];
                        if (nc < 128) v *= 0.17677669529663687f;   // 1/sqrt(32)
                        C[obase + nc] = v;
                    } else if (EPI == 2) {
                        v += bias[nc];
                        C[obase + nc] = v + aux[obase + nc];
                    } else if (EPI == 3) {
                        v += bias[nc];
                        C[obase + nc] = 0.5f * v * (1.0f + erff(v * 0.70710678118654752f));
                    } else { // EPI == 4
                        v += bias[nc];
                        C[obase + nc] = v + aux[obase + nc];
                    }
                }
            }
        }
    }
}

// ---------------- launcher ----------------
extern "C" void kernel_launch(void* const* d_in, const int* in_sizes, int n_in,
                              void* d_out, int out_size)
{
    const float* x       = (const float*)d_in[0];
    const float* n1w     = (const float*)d_in[1];
    const float* n1b     = (const float*)d_in[2];
    const float* qkv_w   = (const float*)d_in[3];
    const float* qkv_b   = (const float*)d_in[4];
    const float* proj_w  = (const float*)d_in[5];
    const float* proj_b  = (const float*)d_in[6];
    const float* rpb     = (const float*)d_in[7];
    const float* n2w     = (const float*)d_in[8];
    const float* n2b     = (const float*)d_in[9];
    const float* fc1_w   = (const float*)d_in[10];
    const float* fc1_b   = (const float*)d_in[11];
    const float* fc2_w   = (const float*)d_in[12];
    const float* fc2_b   = (const float*)d_in[13];
    const float* mnw     = (const float*)d_in[14];
    const float* mnb     = (const float*)d_in[15];
    const float* merge_w = (const float*)d_in[16];
    const int*   rel_idx = (const int*)d_in[17];
    const float* amask   = (const float*)d_in[18];
    float* out = (float*)d_out;

    float *hw, *qkv, *o, *xres, *fc1;
    cudaGetSymbolAddress((void**)&hw,   g_hw);
    cudaGetSymbolAddress((void**)&qkv,  g_qkv);
    cudaGetSymbolAddress((void**)&o,    g_o);
    cudaGetSymbolAddress((void**)&xres, g_xres);
    cudaGetSymbolAddress((void**)&fc1,  g_fc1);

    // 1. LN1 + roll + window partition
    ln1_win_kernel<<<PIX/8, 256>>>(x, n1w, n1b);
    // 2. qkv GEMM (scale folded into q)
    tgemm_kernel<1><<<dim3(384/64, M1_/128), 256>>>(hw, qkv_w, qkv_b, qkv, nullptr, M1_, 384, 128);
    // 3. windowed attention
    attn_kernel<<<dim3(4096, NH_), 64>>>(qkv, rpb, rel_idx, amask, o);
    // 4. proj GEMM + window-reverse + roll-back + residual -> xres (pixel layout)
    tgemm_kernel<2><<<dim3(128/64, M1_/128), 256>>>(o, proj_w, proj_b, xres, x, M1_, 128, 128);
    // 5. LN2: xres -> g_hw (reuse)
    ln2_kernel<<<PIX/8, 256>>>(n2w, n2b);
    // 6. fc1 GEMM + GELU
    tgemm_kernel<3><<<dim3(512/64, M1_/128), 256>>>(hw, fc1_w, fc1_b, fc1, nullptr, M1_, 512, 128);
    // 7. fc2 GEMM + residual (in place on xres)
    tgemm_kernel<4><<<dim3(128/64, M1_/128), 256>>>(fc1, fc2_w, fc2_b, xres, xres, M1_, 128, 512);
    // 8. patch-merge gather + LN(512): xres -> g_o (reuse as xm)
    merge_ln_kernel<<<M2_/8, 256>>>(mnw, mnb);
    // 9. merge GEMM -> output
    tgemm_kernel<0><<<dim3(256/64, M2_/128), 256>>>(o, merge_w, nullptr, out, nullptr, M2_, 256, 512);
}

// round 5
// speedup vs baseline: 2.1695x; 1.1253x over previous
#include <cuda_runtime.h>
#include <math.h>
#include <stdint.h>

// ---------------- problem constants ----------------
#define BATCH 64
#define HS_   56
#define CC    128
#define NH_   4
#define HID_  512
#define PIX   (BATCH*HS_*HS_)      // 200704
#define M1_   PIX                  // window-token rows
#define M2_   (BATCH*28*28)        // 50176 merged rows

// weight scratch offsets (floats)
#define WOFF_QKV   0
#define WOFF_PROJ  49152
#define WOFF_FC1   65536
#define WOFF_FC2   131072
#define WOFF_MRG   196608
#define WTOT       327680

// ---------------- scratch (static device memory; allocation-free) ----------
__device__ float g_hw[(size_t)M1_*CC];       // LN output (tf32-rounded bits)
__device__ float g_qkv[(size_t)M1_*3*CC];    // qkv projections (fp32)
__device__ float g_o[(size_t)M1_*CC];        // attn out / merged xm (tf32-rounded)
__device__ float g_xres[(size_t)M1_*CC];     // residual stream (fp32, pixel layout)
__device__ float g_fc1[(size_t)M1_*HID_];    // fc1+gelu output (tf32-rounded)
__device__ float g_wt[WTOT];                 // tf32-rounded weights

// ---------------- helpers ----------------
__device__ __forceinline__ uint32_t f2tf32(float x) {
    uint32_t r; asm("cvt.rna.tf32.f32 %0, %1;" : "=r"(r) : "f"(x)); return r;
}
__device__ __forceinline__ float tf32r(float x) { return __uint_as_float(f2tf32(x)); }
__device__ __forceinline__ void mma_tf32(float* c, const uint32_t* a, uint32_t b0, uint32_t b1) {
    asm volatile("mma.sync.aligned.m16n8k8.row.col.f32.tf32.tf32.f32 "
        "{%0,%1,%2,%3}, {%4,%5,%6,%7}, {%8,%9}, {%0,%1,%2,%3};\n"
        : "+f"(c[0]), "+f"(c[1]), "+f"(c[2]), "+f"(c[3])
        : "r"(a[0]), "r"(a[1]), "r"(a[2]), "r"(a[3]), "r"(b0), "r"(b1));
}
__device__ __forceinline__ void cp_async16(uint32_t saddr, const void* gptr) {
    asm volatile("cp.async.cg.shared.global [%0], [%1], 16;\n" :: "r"(saddr), "l"(gptr));
}
__device__ __forceinline__ void cp_commit() { asm volatile("cp.async.commit_group;\n"); }
__device__ __forceinline__ void cp_wait1() { asm volatile("cp.async.wait_group 1;\n"); }
__device__ __forceinline__ void cp_wait0() { asm volatile("cp.async.wait_group 0;\n"); }

// ---------------- weight pre-round ----------------
__global__ void round_w_kernel(const float* __restrict__ qkv_w, const float* __restrict__ proj_w,
                               const float* __restrict__ fc1_w, const float* __restrict__ fc2_w,
                               const float* __restrict__ merge_w)
{
    int i = blockIdx.x * blockDim.x + threadIdx.x;
    float v;
    if      (i < WOFF_PROJ) v = qkv_w[i];
    else if (i < WOFF_FC1)  v = proj_w[i - WOFF_PROJ];
    else if (i < WOFF_FC2)  v = fc1_w[i - WOFF_FC1];
    else if (i < WOFF_MRG)  v = fc2_w[i - WOFF_FC2];
    else                    v = merge_w[i - WOFF_MRG];
    g_wt[i] = tf32r(v);
}

// ---------------- LN1 + roll(-3,-3) + window partition (tf32-rounded out) --
__global__ void ln1_win_kernel(const float* __restrict__ x,
                               const float* __restrict__ gw,
                               const float* __restrict__ gb)
{
    int warp = (blockIdx.x * blockDim.x + threadIdx.x) >> 5;
    int lane = threadIdx.x & 31;
    int b   = warp / 3136;
    int rem = warp - b * 3136;
    int i = rem / 56;
    int j = rem - i * 56;
    int si = i + 3; if (si >= 56) si -= 56;
    int sj = j + 3; if (sj >= 56) sj -= 56;
    float4 v = *(const float4*)(x + ((((size_t)b*56 + si)*56) + sj)*128 + lane*4);
    float s  = v.x + v.y + v.z + v.w;
    float ss = v.x*v.x + v.y*v.y + v.z*v.z + v.w*v.w;
    #pragma unroll
    for (int o = 16; o; o >>= 1) {
        s  += __shfl_xor_sync(0xffffffffu, s,  o);
        ss += __shfl_xor_sync(0xffffffffu, ss, o);
    }
    float mean = s * (1.0f/128.0f);
    float var  = ss * (1.0f/128.0f) - mean*mean;
    float rstd = rsqrtf(var + 1e-5f);
    float4 wv = *(const float4*)(gw + lane*4);
    float4 bv = *(const float4*)(gb + lane*4);
    float4 o4;
    o4.x = tf32r((v.x - mean)*rstd*wv.x + bv.x);
    o4.y = tf32r((v.y - mean)*rstd*wv.y + bv.y);
    o4.z = tf32r((v.z - mean)*rstd*wv.z + bv.z);
    o4.w = tf32r((v.w - mean)*rstd*wv.w + bv.w);
    int i7 = i / 7, j7 = j / 7;
    int widx = i7*8 + j7;
    int n    = (i - i7*7)*7 + (j - j7*7);
    size_t row = (size_t)(b*64 + widx)*49 + n;
    *(float4*)(g_hw + row*128 + lane*4) = o4;
}

// ---------------- LN2 (pixel layout): g_xres -> g_hw (tf32-rounded) -------
__global__ void ln2_kernel(const float* __restrict__ gw, const float* __restrict__ gb)
{
    int warp = (blockIdx.x * blockDim.x + threadIdx.x) >> 5;
    int lane = threadIdx.x & 31;
    float4 v = *(const float4*)(g_xres + (size_t)warp*128 + lane*4);
    float s  = v.x + v.y + v.z + v.w;
    float ss = v.x*v.x + v.y*v.y + v.z*v.z + v.w*v.w;
    #pragma unroll
    for (int o = 16; o; o >>= 1) {
        s  += __shfl_xor_sync(0xffffffffu, s,  o);
        ss += __shfl_xor_sync(0xffffffffu, ss, o);
    }
    float mean = s * (1.0f/128.0f);
    float var  = ss * (1.0f/128.0f) - mean*mean;
    float rstd = rsqrtf(var + 1e-5f);
    float4 wv = *(const float4*)(gw + lane*4);
    float4 bv = *(const float4*)(gb + lane*4);
    float4 o4;
    o4.x = tf32r((v.x - mean)*rstd*wv.x + bv.x);
    o4.y = tf32r((v.y - mean)*rstd*wv.y + bv.y);
    o4.z = tf32r((v.z - mean)*rstd*wv.z + bv.z);
    o4.w = tf32r((v.w - mean)*rstd*wv.w + bv.w);
    *(float4*)(g_hw + (size_t)warp*128 + lane*4) = o4;
}

// ---------------- patch-merge gather + LN(512): g_xres -> g_o (rounded) ---
__global__ void merge_ln_kernel(const float* __restrict__ gw, const float* __restrict__ gb)
{
    int warp = (blockIdx.x * blockDim.x + threadIdx.x) >> 5;
    int lane = threadIdx.x & 31;
    int b   = warp / 784;
    int rem = warp - b * 784;
    int i2 = rem / 28;
    int j2 = rem - i2 * 28;
    int i0 = 2*i2, j0 = 2*j2;
    const float* p0 = g_xres + (((size_t)b*56 + i0    )*56 + j0    )*128;
    const float* p1 = g_xres + (((size_t)b*56 + i0 + 1)*56 + j0    )*128;
    const float* p2 = g_xres + (((size_t)b*56 + i0    )*56 + j0 + 1)*128;
    const float* p3 = g_xres + (((size_t)b*56 + i0 + 1)*56 + j0 + 1)*128;
    float4 v[4];
    v[0] = *(const float4*)(p0 + lane*4);
    v[1] = *(const float4*)(p1 + lane*4);
    v[2] = *(const float4*)(p2 + lane*4);
    v[3] = *(const float4*)(p3 + lane*4);
    float s = 0.f, ss = 0.f;
    #pragma unroll
    for (int q = 0; q < 4; q++) {
        s  += v[q].x + v[q].y + v[q].z + v[q].w;
        ss += v[q].x*v[q].x + v[q].y*v[q].y + v[q].z*v[q].z + v[q].w*v[q].w;
    }
    #pragma unroll
    for (int o = 16; o; o >>= 1) {
        s  += __shfl_xor_sync(0xffffffffu, s,  o);
        ss += __shfl_xor_sync(0xffffffffu, ss, o);
    }
    float mean = s * (1.0f/512.0f);
    float var  = ss * (1.0f/512.0f) - mean*mean;
    float rstd = rsqrtf(var + 1e-5f);
    float* out = g_o + (size_t)warp*512;
    #pragma unroll
    for (int q = 0; q < 4; q++) {
        int c = q*128 + lane*4;
        float4 wv = *(const float4*)(gw + c);
        float4 bv = *(const float4*)(gb + c);
        float4 o4;
        o4.x = tf32r((v[q].x - mean)*rstd*wv.x + bv.x);
        o4.y = tf32r((v[q].y - mean)*rstd*wv.y + bv.y);
        o4.z = tf32r((v[q].z - mean)*rstd*wv.z + bv.z);
        o4.w = tf32r((v[q].w - mean)*rstd*wv.w + bv.w);
        *(float4*)(out + c) = o4;
    }
}

// ---------------- attention: one 64-thread block per (window, head) -------
__global__ __launch_bounds__(64) void attn_kernel(
    const float* __restrict__ qkv, const float* __restrict__ rpb,
    const int* __restrict__ rel_index, const float* __restrict__ mask,
    float* __restrict__ outp)
{
    int win = blockIdx.x;
    int h   = blockIdx.y;
    __shared__ float qs[49][33];
    __shared__ float ks[49][32];
    __shared__ float vs[49][32];
    int t = threadIdx.x;
    for (int idx = t; idx < 49*32; idx += 64) {
        int n = idx >> 5, d = idx & 31;
        const float* base = qkv + ((size_t)(win*49 + n))*384 + h*32 + d;
        qs[n][d] = base[0];
        ks[n][d] = base[128];
        vs[n][d] = base[256];
    }
    __syncthreads();
    if (t < 49) {
        float qr[32];
        #pragma unroll
        for (int d = 0; d < 32; d++) qr[d] = qs[t][d];
        int wimg = win & 63;
        const float* mrow = mask + ((size_t)(wimg*49 + t))*49;
        const int*   rrow = rel_index + t*49;
        float s[49];
        float mx = -1e30f;
        #pragma unroll
        for (int m = 0; m < 49; m++) {
            float acc = 0.f;
            #pragma unroll
            for (int d = 0; d < 32; d++) acc += qr[d] * ks[m][d];
            acc += rpb[rrow[m]*4 + h] + mrow[m];
            s[m] = acc;
            mx = fmaxf(mx, acc);
        }
        float sum = 0.f;
        #pragma unroll
        for (int m = 0; m < 49; m++) { s[m] = __expf(s[m] - mx); sum += s[m]; }
        float inv = 1.f / sum;
        float* orow = outp + ((size_t)(win*49 + t))*128 + h*32;
        #pragma unroll
        for (int d = 0; d < 32; d++) {
            float acc = 0.f;
            #pragma unroll
            for (int m = 0; m < 49; m++) acc += s[m] * vs[m][d];
            orow[d] = tf32r(acc * inv);   // rounded: feeds proj GEMM
        }
    }
}

// ---------------- TF32 tensor-core GEMM, cp.async double-buffered ---------
// C[M,Nd] = A[M,K] @ W[Nd,K]^T + epilogue. A and W are PRE-ROUNDED to tf32.
// Block tile 128x128, BK=32, 8 warps (4m x 2n), warp tile 32x64 (mf2 x nf8).
// EPI 0: (+bias if non-null) plain store
// EPI 1: +bias; cols<128 (q) scaled by 1/sqrt(32)
// EPI 2: +bias; window-reverse + roll(+3,+3) scatter; + residual aux (input x)
// EPI 3: +bias; exact GELU; store tf32-rounded (feeds fc2)
// EPI 4: +bias; + residual aux (in-place on g_xres)
#define TG_STG (128*36*2)           // u32 per stage (A pad 36 + B pad 36)
#define TG_SMEM (TG_STG*2*4)        // bytes, two stages = 73728

template<int EPI>
__global__ __launch_bounds__(256, 2) void tgemm_kernel(
    const float* __restrict__ A, const float* __restrict__ W,
    const float* __restrict__ bias, float* __restrict__ C,
    const float* __restrict__ aux, int M, int Nd, int K)
{
    extern __shared__ __align__(16) uint32_t dsm[];
    const int t    = threadIdx.x;
    const int warp = t >> 5;
    const int lane = t & 31;
    const int qr   = lane >> 2;
    const int qc   = lane & 3;
    const int wm   = warp & 3;    // m warp 0..3
    const int wn   = warp >> 2;   // n warp 0..1
    const int bm   = blockIdx.y * 128;
    const int bn   = blockIdx.x * 128;
    const int row0 = t >> 3;      // 0..31
    const int c4   = t & 7;

    const float* aptr = A + (size_t)(bm + row0)*K + c4*4;
    const float* wptr = W + (size_t)(bn + row0)*K + c4*4;
    const size_t rstr = (size_t)32 * K;

    // smem base addresses (as shared-state-space u32)
    uint32_t s_a = (uint32_t)__cvta_generic_to_shared(dsm);
    uint32_t s_b = s_a + 128*36*4;

    float acc[2][8][4] = {};

    const int iters = K >> 5;
    // prologue: stage 0
    {
        #pragma unroll
        for (int l = 0; l < 4; l++)
            cp_async16(s_a + ((row0 + l*32)*36 + c4*4)*4, aptr + l*rstr);
        #pragma unroll
        for (int l = 0; l < 4; l++)
            cp_async16(s_b + ((row0 + l*32)*36 + c4*4)*4, wptr + l*rstr);
        cp_commit();
    }

    for (int it = 0; it < iters; it++) {
        if (it + 1 < iters) {
            uint32_t sa = s_a + ((it+1)&1)*TG_STG*4;
            uint32_t sb = s_b + ((it+1)&1)*TG_STG*4;
            const float* ap = aptr + (size_t)(it+1)*32;
            const float* wp = wptr + (size_t)(it+1)*32;
            #pragma unroll
            for (int l = 0; l < 4; l++)
                cp_async16(sa + ((row0 + l*32)*36 + c4*4)*4, ap + l*rstr);
            #pragma unroll
            for (int l = 0; l < 4; l++)
                cp_async16(sb + ((row0 + l*32)*36 + c4*4)*4, wp + l*rstr);
            cp_commit();
            cp_wait1();
        } else {
            cp_wait0();
        }
        __syncthreads();

        const uint32_t* As = dsm + (it&1)*TG_STG;
        const uint32_t* Bs = As + 128*36;
        #pragma unroll
        for (int ks = 0; ks < 4; ks++) {
            const int kb = ks * 8;
            uint32_t af[2][4];
            #pragma unroll
            for (int i = 0; i < 2; i++) {
                int m0 = wm*32 + i*16 + qr;
                af[i][0] = As[ m0     *36 + kb + qc    ];
                af[i][1] = As[(m0 + 8)*36 + kb + qc    ];
                af[i][2] = As[ m0     *36 + kb + qc + 4];
                af[i][3] = As[(m0 + 8)*36 + kb + qc + 4];
            }
            #pragma unroll
            for (int j = 0; j < 8; j++) {
                int n0 = wn*64 + j*8 + qr;
                uint32_t b0 = Bs[n0*36 + kb + qc    ];
                uint32_t b1 = Bs[n0*36 + kb + qc + 4];
                mma_tf32(acc[0][j], af[0], b0, b1);
                mma_tf32(acc[1][j], af[1], b0, b1);
            }
        }
        __syncthreads();
    }

    // ---- epilogue ----
    #pragma unroll
    for (int i = 0; i < 2; i++) {
        #pragma unroll
        for (int half = 0; half < 2; half++) {
            const int m = bm + wm*32 + i*16 + qr + half*8;
            size_t obase;
            if (EPI == 2) {
                int win = m / 49, nn = m - win*49;
                int bb = win >> 6, w = win & 63;
                int n7 = nn / 7;
                int pi = (w >> 3)*7 + n7;
                int pj = (w & 7)*7 + (nn - n7*7);
                int ii = pi + 3; if (ii >= 56) ii -= 56;
                int jj = pj + 3; if (jj >= 56) jj -= 56;
                obase = (((size_t)bb*56 + ii)*56 + jj)*128;
            } else {
                obase = (size_t)m * Nd;
            }
            #pragma unroll
            for (int j = 0; j < 8; j++) {
                const int n = bn + wn*64 + j*8 + qc*2;
                #pragma unroll
                for (int e = 0; e < 2; e++) {
                    const int nc = n + e;
                    float v = acc[i][j][half*2 + e];
                    if (EPI == 0) {
                        if (bias) v += bias[nc];
                        C[obase + nc] = v;
                    } else if (EPI == 1) {
                        v += bias[nc];
                        if (nc < 128) v *= 0.17677669529663687f;   // 1/sqrt(32)
                        C[obase + nc] = v;
                    } else if (EPI == 2) {
                        v += bias[nc];
                        C[obase + nc] = v + aux[obase + nc];
                    } else if (EPI == 3) {
                        v += bias[nc];
                        C[obase + nc] = tf32r(0.5f * v * (1.0f + erff(v * 0.70710678118654752f)));
                    } else { // EPI == 4
                        v += bias[nc];
                        C[obase + nc] = v + aux[obase + nc];
                    }
                }
            }
        }
    }
}

// ---------------- launcher ----------------
extern "C" void kernel_launch(void* const* d_in, const int* in_sizes, int n_in,
                              void* d_out, int out_size)
{
    const float* x       = (const float*)d_in[0];
    const float* n1w     = (const float*)d_in[1];
    const float* n1b     = (const float*)d_in[2];
    const float* qkv_w   = (const float*)d_in[3];
    const float* qkv_b   = (const float*)d_in[4];
    const float* proj_w  = (const float*)d_in[5];
    const float* proj_b  = (const float*)d_in[6];
    const float* rpb     = (const float*)d_in[7];
    const float* n2w     = (const float*)d_in[8];
    const float* n2b     = (const float*)d_in[9];
    const float* fc1_w   = (const float*)d_in[10];
    const float* fc1_b   = (const float*)d_in[11];
    const float* fc2_w   = (const float*)d_in[12];
    const float* fc2_b   = (const float*)d_in[13];
    const float* mnw     = (const float*)d_in[14];
    const float* mnb     = (const float*)d_in[15];
    const float* merge_w = (const float*)d_in[16];
    const int*   rel_idx = (const int*)d_in[17];
    const float* amask   = (const float*)d_in[18];
    float* out = (float*)d_out;

    float *hw, *qkv, *o, *xres, *fc1, *wt;
    cudaGetSymbolAddress((void**)&hw,   g_hw);
    cudaGetSymbolAddress((void**)&qkv,  g_qkv);
    cudaGetSymbolAddress((void**)&o,    g_o);
    cudaGetSymbolAddress((void**)&xres, g_xres);
    cudaGetSymbolAddress((void**)&fc1,  g_fc1);
    cudaGetSymbolAddress((void**)&wt,   g_wt);

    cudaFuncSetAttribute(tgemm_kernel<0>, cudaFuncAttributeMaxDynamicSharedMemorySize, TG_SMEM);
    cudaFuncSetAttribute(tgemm_kernel<1>, cudaFuncAttributeMaxDynamicSharedMemorySize, TG_SMEM);
    cudaFuncSetAttribute(tgemm_kernel<2>, cudaFuncAttributeMaxDynamicSharedMemorySize, TG_SMEM);
    cudaFuncSetAttribute(tgemm_kernel<3>, cudaFuncAttributeMaxDynamicSharedMemorySize, TG_SMEM);
    cudaFuncSetAttribute(tgemm_kernel<4>, cudaFuncAttributeMaxDynamicSharedMemorySize, TG_SMEM);

    // 0. pre-round weights to tf32
    round_w_kernel<<<WTOT/256, 256>>>(qkv_w, proj_w, fc1_w, fc2_w, merge_w);
    // 1. LN1 + roll + window partition (rounded)
    ln1_win_kernel<<<PIX/8, 256>>>(x, n1w, n1b);
    // 2. qkv GEMM (scale folded into q)
    tgemm_kernel<1><<<dim3(3, M1_/128), 256, TG_SMEM>>>(hw, wt + WOFF_QKV, qkv_b, qkv, nullptr, M1_, 384, 128);
    // 3. windowed attention (rounded out)
    attn_kernel<<<dim3(4096, NH_), 64>>>(qkv, rpb, rel_idx, amask, o);
    // 4. proj GEMM + window-reverse + roll-back + residual -> xres (pixel layout)
    tgemm_kernel<2><<<dim3(1, M1_/128), 256, TG_SMEM>>>(o, wt + WOFF_PROJ, proj_b, xres, x, M1_, 128, 128);
    // 5. LN2: xres -> g_hw (rounded)
    ln2_kernel<<<PIX/8, 256>>>(n2w, n2b);
    // 6. fc1 GEMM + GELU (rounded out)
    tgemm_kernel<3><<<dim3(4, M1_/128), 256, TG_SMEM>>>(hw, wt + WOFF_FC1, fc1_b, fc1, nullptr, M1_, 512, 128);
    // 7. fc2 GEMM + residual (in place on xres)
    tgemm_kernel<4><<<dim3(1, M1_/128), 256, TG_SMEM>>>(fc1, wt + WOFF_FC2, fc2_b, xres, xres, M1_, 128, 512);
    // 8. patch-merge gather + LN(512): xres -> g_o (rounded, reuse as xm)
    merge_ln_kernel<<<M2_/8, 256>>>(mnw, mnb);
    // 9. merge GEMM -> output
    tgemm_kernel<0><<<dim3(2, M2_/128), 256, TG_SMEM>>>(o, wt + WOFF_MRG, nullptr, out, nullptr, M2_, 256, 512);
}

// round 6
// speedup vs baseline: 2.3220x; 1.0703x over previous
#include <cuda_runtime.h>
#include <math.h>
#include <stdint.h>

// ---------------- problem constants ----------------
#define BATCH 64
#define HS_   56
#define CC    128
#define NH_   4
#define HID_  512
#define PIX   (BATCH*HS_*HS_)      // 200704
#define M1_   PIX                  // window-token rows
#define M2_   (BATCH*28*28)        // 50176 merged rows

// weight scratch offsets (floats)
#define WOFF_QKV   0
#define WOFF_PROJ  49152
#define WOFF_FC1   65536
#define WOFF_FC2   131072
#define WOFF_MRG   196608
#define WTOT       327680

// ---------------- scratch (static device memory; allocation-free) ----------
__device__ float g_hw[(size_t)M1_*CC];       // LN output (tf32-rounded bits)
__device__ float g_qkv[(size_t)M1_*3*CC];    // qkv projections (tf32-rounded)
__device__ float g_o[(size_t)M1_*CC];        // attn out / merged xm (tf32-rounded)
__device__ float g_xres[(size_t)M1_*CC];     // residual stream (fp32, pixel layout)
__device__ float g_fc1[(size_t)M1_*HID_];    // fc1+gelu output (tf32-rounded)
__device__ float g_wt[WTOT];                 // tf32-rounded weights
__device__ float g_bias[64*4*2401];          // combined rpb+mask per (wimg, head)

// ---------------- helpers ----------------
__device__ __forceinline__ uint32_t f2tf32(float x) {
    uint32_t r; asm("cvt.rna.tf32.f32 %0, %1;" : "=r"(r) : "f"(x)); return r;
}
__device__ __forceinline__ float tf32r(float x) { return __uint_as_float(f2tf32(x)); }
__device__ __forceinline__ void mma_tf32(float* c, const uint32_t* a, uint32_t b0, uint32_t b1) {
    asm volatile("mma.sync.aligned.m16n8k8.row.col.f32.tf32.tf32.f32 "
        "{%0,%1,%2,%3}, {%4,%5,%6,%7}, {%8,%9}, {%0,%1,%2,%3};\n"
        : "+f"(c[0]), "+f"(c[1]), "+f"(c[2]), "+f"(c[3])
        : "r"(a[0]), "r"(a[1]), "r"(a[2]), "r"(a[3]), "r"(b0), "r"(b1));
}
__device__ __forceinline__ void cp_async16(uint32_t saddr, const void* gptr) {
    asm volatile("cp.async.cg.shared.global [%0], [%1], 16;\n" :: "r"(saddr), "l"(gptr));
}
__device__ __forceinline__ void cp_commit() { asm volatile("cp.async.commit_group;\n"); }
__device__ __forceinline__ void cp_wait1() { asm volatile("cp.async.wait_group 1;\n"); }
__device__ __forceinline__ void cp_wait0() { asm volatile("cp.async.wait_group 0;\n"); }

// ---------------- weight pre-round ----------------
__global__ void round_w_kernel(const float* __restrict__ qkv_w, const float* __restrict__ proj_w,
                               const float* __restrict__ fc1_w, const float* __restrict__ fc2_w,
                               const float* __restrict__ merge_w)
{
    int i = blockIdx.x * blockDim.x + threadIdx.x;
    float v;
    if      (i < WOFF_PROJ) v = qkv_w[i];
    else if (i < WOFF_FC1)  v = proj_w[i - WOFF_PROJ];
    else if (i < WOFF_FC2)  v = fc1_w[i - WOFF_FC1];
    else if (i < WOFF_MRG)  v = fc2_w[i - WOFF_FC2];
    else                    v = merge_w[i - WOFF_MRG];
    g_wt[i] = tf32r(v);
}

// ---------------- combined attention bias table: rpb[rel]+mask ------------
__global__ void bias_prep_kernel(const float* __restrict__ rpb,
                                 const int* __restrict__ rel,
                                 const float* __restrict__ mask)
{
    int wimg = blockIdx.x, h = blockIdx.y;
    float* dst = g_bias + ((size_t)wimg*4 + h)*2401;
    const float* msk = mask + (size_t)wimg*2401;
    for (int i = threadIdx.x; i < 2401; i += blockDim.x)
        dst[i] = rpb[rel[i]*4 + h] + msk[i];
}

// ---------------- LN1 + roll(-3,-3) + window partition (tf32-rounded out) --
__global__ void ln1_win_kernel(const float* __restrict__ x,
                               const float* __restrict__ gw,
                               const float* __restrict__ gb)
{
    int warp = (blockIdx.x * blockDim.x + threadIdx.x) >> 5;
    int lane = threadIdx.x & 31;
    int b   = warp / 3136;
    int rem = warp - b * 3136;
    int i = rem / 56;
    int j = rem - i * 56;
    int si = i + 3; if (si >= 56) si -= 56;
    int sj = j + 3; if (sj >= 56) sj -= 56;
    float4 v = *(const float4*)(x + ((((size_t)b*56 + si)*56) + sj)*128 + lane*4);
    float s  = v.x + v.y + v.z + v.w;
    float ss = v.x*v.x + v.y*v.y + v.z*v.z + v.w*v.w;
    #pragma unroll
    for (int o = 16; o; o >>= 1) {
        s  += __shfl_xor_sync(0xffffffffu, s,  o);
        ss += __shfl_xor_sync(0xffffffffu, ss, o);
    }
    float mean = s * (1.0f/128.0f);
    float var  = ss * (1.0f/128.0f) - mean*mean;
    float rstd = rsqrtf(var + 1e-5f);
    float4 wv = *(const float4*)(gw + lane*4);
    float4 bv = *(const float4*)(gb + lane*4);
    float4 o4;
    o4.x = tf32r((v.x - mean)*rstd*wv.x + bv.x);
    o4.y = tf32r((v.y - mean)*rstd*wv.y + bv.y);
    o4.z = tf32r((v.z - mean)*rstd*wv.z + bv.z);
    o4.w = tf32r((v.w - mean)*rstd*wv.w + bv.w);
    int i7 = i / 7, j7 = j / 7;
    int widx = i7*8 + j7;
    int n    = (i - i7*7)*7 + (j - j7*7);
    size_t row = (size_t)(b*64 + widx)*49 + n;
    *(float4*)(g_hw + row*128 + lane*4) = o4;
}

// ---------------- LN2 (pixel layout): g_xres -> g_hw (tf32-rounded) -------
__global__ void ln2_kernel(const float* __restrict__ gw, const float* __restrict__ gb)
{
    int warp = (blockIdx.x * blockDim.x + threadIdx.x) >> 5;
    int lane = threadIdx.x & 31;
    float4 v = *(const float4*)(g_xres + (size_t)warp*128 + lane*4);
    float s  = v.x + v.y + v.z + v.w;
    float ss = v.x*v.x + v.y*v.y + v.z*v.z + v.w*v.w;
    #pragma unroll
    for (int o = 16; o; o >>= 1) {
        s  += __shfl_xor_sync(0xffffffffu, s,  o);
        ss += __shfl_xor_sync(0xffffffffu, ss, o);
    }
    float mean = s * (1.0f/128.0f);
    float var  = ss * (1.0f/128.0f) - mean*mean;
    float rstd = rsqrtf(var + 1e-5f);
    float4 wv = *(const float4*)(gw + lane*4);
    float4 bv = *(const float4*)(gb + lane*4);
    float4 o4;
    o4.x = tf32r((v.x - mean)*rstd*wv.x + bv.x);
    o4.y = tf32r((v.y - mean)*rstd*wv.y + bv.y);
    o4.z = tf32r((v.z - mean)*rstd*wv.z + bv.z);
    o4.w = tf32r((v.w - mean)*rstd*wv.w + bv.w);
    *(float4*)(g_hw + (size_t)warp*128 + lane*4) = o4;
}

// ---------------- patch-merge gather + LN(512): g_xres -> g_o (rounded) ---
__global__ void merge_ln_kernel(const float* __restrict__ gw, const float* __restrict__ gb)
{
    int warp = (blockIdx.x * blockDim.x + threadIdx.x) >> 5;
    int lane = threadIdx.x & 31;
    int b   = warp / 784;
    int rem = warp - b * 784;
    int i2 = rem / 28;
    int j2 = rem - i2 * 28;
    int i0 = 2*i2, j0 = 2*j2;
    const float* p0 = g_xres + (((size_t)b*56 + i0    )*56 + j0    )*128;
    const float* p1 = g_xres + (((size_t)b*56 + i0 + 1)*56 + j0    )*128;
    const float* p2 = g_xres + (((size_t)b*56 + i0    )*56 + j0 + 1)*128;
    const float* p3 = g_xres + (((size_t)b*56 + i0 + 1)*56 + j0 + 1)*128;
    float4 v[4];
    v[0] = *(const float4*)(p0 + lane*4);
    v[1] = *(const float4*)(p1 + lane*4);
    v[2] = *(const float4*)(p2 + lane*4);
    v[3] = *(const float4*)(p3 + lane*4);
    float s = 0.f, ss = 0.f;
    #pragma unroll
    for (int q = 0; q < 4; q++) {
        s  += v[q].x + v[q].y + v[q].z + v[q].w;
        ss += v[q].x*v[q].x + v[q].y*v[q].y + v[q].z*v[q].z + v[q].w*v[q].w;
    }
    #pragma unroll
    for (int o = 16; o; o >>= 1) {
        s  += __shfl_xor_sync(0xffffffffu, s,  o);
        ss += __shfl_xor_sync(0xffffffffu, ss, o);
    }
    float mean = s * (1.0f/512.0f);
    float var  = ss * (1.0f/512.0f) - mean*mean;
    float rstd = rsqrtf(var + 1e-5f);
    float* out = g_o + (size_t)warp*512;
    #pragma unroll
    for (int q = 0; q < 4; q++) {
        int c = q*128 + lane*4;
        float4 wv = *(const float4*)(gw + c);
        float4 bv = *(const float4*)(gb + c);
        float4 o4;
        o4.x = tf32r((v[q].x - mean)*rstd*wv.x + bv.x);
        o4.y = tf32r((v[q].y - mean)*rstd*wv.y + bv.y);
        o4.z = tf32r((v[q].z - mean)*rstd*wv.z + bv.z);
        o4.w = tf32r((v[q].w - mean)*rstd*wv.w + bv.w);
        *(float4*)(out + c) = o4;
    }
}

// ---------------- MMA attention: block = one window, warp = one head ------
// Per head: S = Q K^T padded 64x56x32 (tf32 mma), register softmax with
// precomputed bias table, P -> smem, O = P V (64x32x56). q scale folded (EPI1).
#define AQ_STR 132
#define AK_STR 132
#define AV_STR 136
#define AP_STR 60
#define AOFF_K (64*AQ_STR)                  // 8448
#define AOFF_V (AOFF_K + 56*AK_STR)         // 15840
#define AOFF_P (AOFF_V + 56*AV_STR)         // 23456
#define AOFF_I (AOFF_P + 4*16*AP_STR)       // 27296
#define ATT_SMEM ((AOFF_I + 4*16)*4)        // 109440 bytes

__global__ __launch_bounds__(128) void attn_kernel(
    const float* __restrict__ qkv, float* __restrict__ outp)
{
    extern __shared__ float sm[];
    float* qs = sm;
    float* ks = sm + AOFF_K;
    float* vs = sm + AOFF_V;
    const int t    = threadIdx.x;
    const int warp = t >> 5;
    const int lane = t & 31;
    const int win  = blockIdx.x;
    float* Pt   = sm + AOFF_P + warp*16*AP_STR;
    float* invs = sm + AOFF_I + warp*16;

    // ---- load Q/K/V for the whole window (all heads), coalesced ----
    const float* base = qkv + (size_t)win*49*384;
    for (int idx = t; idx < 49*96; idx += 128) {
        int row = idx / 96;
        int sub = idx - row*96;
        int kind = sub >> 5;
        int c4 = sub & 31;
        float4 v = *(const float4*)(base + (size_t)row*384 + kind*128 + c4*4);
        float* dst = (kind == 0 ? qs + row*AQ_STR :
                      kind == 1 ? ks + row*AK_STR : vs + row*AV_STR) + c4*4;
        *(float4*)dst = v;
    }
    // zero K/V pad rows 49..55 (padded N/K dims must contribute exact zeros)
    for (int idx = t; idx < 7*AV_STR; idx += 128) {
        int r = idx / AV_STR, c = idx - r*AV_STR;
        vs[(49+r)*AV_STR + c] = 0.f;
        if (c < AK_STR) ks[(49+r)*AK_STR + c] = 0.f;
    }
    __syncthreads();

    const int h   = warp;
    const int qr  = lane >> 2;
    const int qc  = lane & 3;
    const int h32 = h * 32;
    const float* comb = g_bias + (size_t)((win & 63)*4 + h)*2401;
    float* obase = outp + (size_t)win*49*128 + h32;

    for (int mt = 0; mt < 4; mt++) {
        const int r0 = mt*16 + qr;        // row of this lane (half 0)
        const int r1 = r0 + 8;            // row (half 1)
        // ---- mma #1: S[16 x 56] = Q_tile @ K^T ----
        float s[7][4];
        #pragma unroll
        for (int jn = 0; jn < 7; jn++)
            #pragma unroll
            for (int c = 0; c < 4; c++) s[jn][c] = 0.f;
        #pragma unroll
        for (int kb = 0; kb < 32; kb += 8) {
            uint32_t a[4];
            a[0] = __float_as_uint(qs[(size_t)r0*AQ_STR + h32 + kb + qc    ]);
            a[1] = __float_as_uint(qs[(size_t)r1*AQ_STR + h32 + kb + qc    ]);
            a[2] = __float_as_uint(qs[(size_t)r0*AQ_STR + h32 + kb + qc + 4]);
            a[3] = __float_as_uint(qs[(size_t)r1*AQ_STR + h32 + kb + qc + 4]);
            #pragma unroll
            for (int jn = 0; jn < 7; jn++) {
                int n0 = jn*8 + qr;
                uint32_t b0 = __float_as_uint(ks[(size_t)n0*AK_STR + h32 + kb + qc    ]);
                uint32_t b1 = __float_as_uint(ks[(size_t)n0*AK_STR + h32 + kb + qc + 4]);
                mma_tf32(s[jn], a, b0, b1);
            }
        }
        // ---- bias + register softmax (rows r0, r1) ----
        const bool v0 = (r0 < 49), v1 = (r1 < 49);
        float mx0 = -1e30f, mx1 = -1e30f;
        #pragma unroll
        for (int jn = 0; jn < 7; jn++) {
            #pragma unroll
            for (int e = 0; e < 2; e++) {
                int col = jn*8 + qc*2 + e;
                if (col < 49) {
                    if (v0) s[jn][e]     += comb[r0*49 + col];
                    if (v1) s[jn][2 + e] += comb[r1*49 + col];
                } else {
                    s[jn][e] = -1e30f; s[jn][2 + e] = -1e30f;
                }
                mx0 = fmaxf(mx0, s[jn][e]);
                mx1 = fmaxf(mx1, s[jn][2 + e]);
            }
        }
        #pragma unroll
        for (int o = 1; o <= 2; o <<= 1) {
            mx0 = fmaxf(mx0, __shfl_xor_sync(0xffffffffu, mx0, o));
            mx1 = fmaxf(mx1, __shfl_xor_sync(0xffffffffu, mx1, o));
        }
        float sum0 = 0.f, sum1 = 0.f;
        #pragma unroll
        for (int jn = 0; jn < 7; jn++) {
            #pragma unroll
            for (int e = 0; e < 2; e++) {
                int col = jn*8 + qc*2 + e;
                float e0 = __expf(s[jn][e]     - mx0);
                float e1 = __expf(s[jn][2 + e] - mx1);
                sum0 += e0; sum1 += e1;
                Pt[qr*AP_STR       + col] = tf32r(e0);
                Pt[(qr + 8)*AP_STR + col] = tf32r(e1);
            }
        }
        #pragma unroll
        for (int o = 1; o <= 2; o <<= 1) {
            sum0 += __shfl_xor_sync(0xffffffffu, sum0, o);
            sum1 += __shfl_xor_sync(0xffffffffu, sum1, o);
        }
        if (qc == 0) {
            invs[qr]     = 1.0f / sum0;
            invs[qr + 8] = 1.0f / sum1;
        }
        __syncwarp();
        // ---- mma #2: O[16 x 32] = P @ V ----
        float o[4][4];
        #pragma unroll
        for (int jn = 0; jn < 4; jn++)
            #pragma unroll
            for (int c = 0; c < 4; c++) o[jn][c] = 0.f;
        #pragma unroll
        for (int ks2 = 0; ks2 < 7; ks2++) {
            const int kb = ks2*8;
            uint32_t a[4];
            a[0] = __float_as_uint(Pt[qr*AP_STR       + kb + qc    ]);
            a[1] = __float_as_uint(Pt[(qr + 8)*AP_STR + kb + qc    ]);
            a[2] = __float_as_uint(Pt[qr*AP_STR       + kb + qc + 4]);
            a[3] = __float_as_uint(Pt[(qr + 8)*AP_STR + kb + qc + 4]);
            #pragma unroll
            for (int jn = 0; jn < 4; jn++) {
                int n0 = jn*8 + qr;
                uint32_t b0 = __float_as_uint(vs[(size_t)(kb + qc    )*AV_STR + h32 + n0]);
                uint32_t b1 = __float_as_uint(vs[(size_t)(kb + qc + 4)*AV_STR + h32 + n0]);
                mma_tf32(o[jn], a, b0, b1);
            }
        }
        // ---- normalize + store ----
        float i0 = invs[qr], i1 = invs[qr + 8];
        #pragma unroll
        for (int jn = 0; jn < 4; jn++) {
            int col = jn*8 + qc*2;
            if (v0) {
                float2 f; f.x = tf32r(o[jn][0]*i0); f.y = tf32r(o[jn][1]*i0);
                *(float2*)(obase + (size_t)r0*128 + col) = f;
            }
            if (v1) {
                float2 f; f.x = tf32r(o[jn][2]*i1); f.y = tf32r(o[jn][3]*i1);
                *(float2*)(obase + (size_t)r1*128 + col) = f;
            }
        }
        __syncwarp();   // Pt reused next m-tile
    }
}

// ---------------- TF32 tensor-core GEMM, cp.async double-buffered ---------
// C[M,Nd] = A[M,K] @ W[Nd,K]^T + epilogue. A and W are PRE-ROUNDED to tf32.
// Block tile 128x128, BK=32, 8 warps (4m x 2n), warp tile 32x64 (mf2 x nf8).
// EPI 0: (+bias if non-null) plain store
// EPI 1: +bias; cols<128 (q) scaled by 1/sqrt(32); store tf32-rounded
// EPI 2: +bias; window-reverse + roll(+3,+3) scatter; + residual aux (input x)
// EPI 3: +bias; exact GELU; store tf32-rounded (feeds fc2)
// EPI 4: +bias; + residual aux (in-place on g_xres)
#define TG_STG (128*36*2)           // u32 per stage (A pad 36 + B pad 36)
#define TG_SMEM (TG_STG*2*4)        // bytes, two stages = 73728

template<int EPI>
__global__ __launch_bounds__(256, 2) void tgemm_kernel(
    const float* __restrict__ A, const float* __restrict__ W,
    const float* __restrict__ bias, float* __restrict__ C,
    const float* __restrict__ aux, int M, int Nd, int K)
{
    extern __shared__ __align__(16) uint32_t dsm[];
    const int t    = threadIdx.x;
    const int warp = t >> 5;
    const int lane = t & 31;
    const int qr   = lane >> 2;
    const int qc   = lane & 3;
    const int wm   = warp & 3;    // m warp 0..3
    const int wn   = warp >> 2;   // n warp 0..1
    const int bm   = blockIdx.y * 128;
    const int bn   = blockIdx.x * 128;
    const int row0 = t >> 3;      // 0..31
    const int c4   = t & 7;

    const float* aptr = A + (size_t)(bm + row0)*K + c4*4;
    const float* wptr = W + (size_t)(bn + row0)*K + c4*4;
    const size_t rstr = (size_t)32 * K;

    uint32_t s_a = (uint32_t)__cvta_generic_to_shared(dsm);
    uint32_t s_b = s_a + 128*36*4;

    float acc[2][8][4] = {};

    const int iters = K >> 5;
    {
        #pragma unroll
        for (int l = 0; l < 4; l++)
            cp_async16(s_a + ((row0 + l*32)*36 + c4*4)*4, aptr + l*rstr);
        #pragma unroll
        for (int l = 0; l < 4; l++)
            cp_async16(s_b + ((row0 + l*32)*36 + c4*4)*4, wptr + l*rstr);
        cp_commit();
    }

    for (int it = 0; it < iters; it++) {
        if (it + 1 < iters) {
            uint32_t sa = s_a + ((it+1)&1)*TG_STG*4;
            uint32_t sb = s_b + ((it+1)&1)*TG_STG*4;
            const float* ap = aptr + (size_t)(it+1)*32;
            const float* wp = wptr + (size_t)(it+1)*32;
            #pragma unroll
            for (int l = 0; l < 4; l++)
                cp_async16(sa + ((row0 + l*32)*36 + c4*4)*4, ap + l*rstr);
            #pragma unroll
            for (int l = 0; l < 4; l++)
                cp_async16(sb + ((row0 + l*32)*36 + c4*4)*4, wp + l*rstr);
            cp_commit();
            cp_wait1();
        } else {
            cp_wait0();
        }
        __syncthreads();

        const uint32_t* As = dsm + (it&1)*TG_STG;
        const uint32_t* Bs = As + 128*36;
        #pragma unroll
        for (int ks = 0; ks < 4; ks++) {
            const int kb = ks * 8;
            uint32_t af[2][4];
            #pragma unroll
            for (int i = 0; i < 2; i++) {
                int m0 = wm*32 + i*16 + qr;
                af[i][0] = As[ m0     *36 + kb + qc    ];
                af[i][1] = As[(m0 + 8)*36 + kb + qc    ];
                af[i][2] = As[ m0     *36 + kb + qc + 4];
                af[i][3] = As[(m0 + 8)*36 + kb + qc + 4];
            }
            #pragma unroll
            for (int j = 0; j < 8; j++) {
                int n0 = wn*64 + j*8 + qr;
                uint32_t b0 = Bs[n0*36 + kb + qc    ];
                uint32_t b1 = Bs[n0*36 + kb + qc + 4];
                mma_tf32(acc[0][j], af[0], b0, b1);
                mma_tf32(acc[1][j], af[1], b0, b1);
            }
        }
        __syncthreads();
    }

    // ---- epilogue ----
    #pragma unroll
    for (int i = 0; i < 2; i++) {
        #pragma unroll
        for (int half = 0; half < 2; half++) {
            const int m = bm + wm*32 + i*16 + qr + half*8;
            size_t obase;
            if (EPI == 2) {
                int win = m / 49, nn = m - win*49;
                int bb = win >> 6, w = win & 63;
                int n7 = nn / 7;
                int pi = (w >> 3)*7 + n7;
                int pj = (w & 7)*7 + (nn - n7*7);
                int ii = pi + 3; if (ii >= 56) ii -= 56;
                int jj = pj + 3; if (jj >= 56) jj -= 56;
                obase = (((size_t)bb*56 + ii)*56 + jj)*128;
            } else {
                obase = (size_t)m * Nd;
            }
            #pragma unroll
            for (int j = 0; j < 8; j++) {
                const int n = bn + wn*64 + j*8 + qc*2;
                #pragma unroll
                for (int e = 0; e < 2; e++) {
                    const int nc = n + e;
                    float v = acc[i][j][half*2 + e];
                    if (EPI == 0) {
                        if (bias) v += bias[nc];
                        C[obase + nc] = v;
                    } else if (EPI == 1) {
                        v += bias[nc];
                        if (nc < 128) v *= 0.17677669529663687f;   // 1/sqrt(32)
                        C[obase + nc] = tf32r(v);
                    } else if (EPI == 2) {
                        v += bias[nc];
                        C[obase + nc] = v + aux[obase + nc];
                    } else if (EPI == 3) {
                        v += bias[nc];
                        C[obase + nc] = tf32r(0.5f * v * (1.0f + erff(v * 0.70710678118654752f)));
                    } else { // EPI == 4
                        v += bias[nc];
                        C[obase + nc] = v + aux[obase + nc];
                    }
                }
            }
        }
    }
}

// ---------------- launcher ----------------
extern "C" void kernel_launch(void* const* d_in, const int* in_sizes, int n_in,
                              void* d_out, int out_size)
{
    const float* x       = (const float*)d_in[0];
    const float* n1w     = (const float*)d_in[1];
    const float* n1b     = (const float*)d_in[2];
    const float* qkv_w   = (const float*)d_in[3];
    const float* qkv_b   = (const float*)d_in[4];
    const float* proj_w  = (const float*)d_in[5];
    const float* proj_b  = (const float*)d_in[6];
    const float* rpb     = (const float*)d_in[7];
    const float* n2w     = (const float*)d_in[8];
    const float* n2b     = (const float*)d_in[9];
    const float* fc1_w   = (const float*)d_in[10];
    const float* fc1_b   = (const float*)d_in[11];
    const float* fc2_w   = (const float*)d_in[12];
    const float* fc2_b   = (const float*)d_in[13];
    const float* mnw     = (const float*)d_in[14];
    const float* mnb     = (const float*)d_in[15];
    const float* merge_w = (const float*)d_in[16];
    const int*   rel_idx = (const int*)d_in[17];
    const float* amask   = (const float*)d_in[18];
    float* out = (float*)d_out;

    float *hw, *qkv, *o, *xres, *fc1, *wt;
    cudaGetSymbolAddress((void**)&hw,   g_hw);
    cudaGetSymbolAddress((void**)&qkv,  g_qkv);
    cudaGetSymbolAddress((void**)&o,    g_o);
    cudaGetSymbolAddress((void**)&xres, g_xres);
    cudaGetSymbolAddress((void**)&fc1,  g_fc1);
    cudaGetSymbolAddress((void**)&wt,   g_wt);

    cudaFuncSetAttribute(tgemm_kernel<0>, cudaFuncAttributeMaxDynamicSharedMemorySize, TG_SMEM);
    cudaFuncSetAttribute(tgemm_kernel<1>, cudaFuncAttributeMaxDynamicSharedMemorySize, TG_SMEM);
    cudaFuncSetAttribute(tgemm_kernel<2>, cudaFuncAttributeMaxDynamicSharedMemorySize, TG_SMEM);
    cudaFuncSetAttribute(tgemm_kernel<3>, cudaFuncAttributeMaxDynamicSharedMemorySize, TG_SMEM);
    cudaFuncSetAttribute(tgemm_kernel<4>, cudaFuncAttributeMaxDynamicSharedMemorySize, TG_SMEM);
    cudaFuncSetAttribute(attn_kernel, cudaFuncAttributeMaxDynamicSharedMemorySize, ATT_SMEM);

    // 0. pre-round weights; build combined attention bias table
    round_w_kernel<<<WTOT/256, 256>>>(qkv_w, proj_w, fc1_w, fc2_w, merge_w);
    bias_prep_kernel<<<dim3(64, 4), 256>>>(rpb, rel_idx, amask);
    // 1. LN1 + roll + window partition (rounded)
    ln1_win_kernel<<<PIX/8, 256>>>(x, n1w, n1b);
    // 2. qkv GEMM (scale folded into q; rounded out)
    tgemm_kernel<1><<<dim3(3, M1_/128), 256, TG_SMEM>>>(hw, wt + WOFF_QKV, qkv_b, qkv, nullptr, M1_, 384, 128);
    // 3. windowed attention (tensor cores; rounded out)
    attn_kernel<<<4096, 128, ATT_SMEM>>>(qkv, o);
    // 4. proj GEMM + window-reverse + roll-back + residual -> xres (pixel layout)
    tgemm_kernel<2><<<dim3(1, M1_/128), 256, TG_SMEM>>>(o, wt + WOFF_PROJ, proj_b, xres, x, M1_, 128, 128);
    // 5. LN2: xres -> g_hw (rounded)
    ln2_kernel<<<PIX/8, 256>>>(n2w, n2b);
    // 6. fc1 GEMM + GELU (rounded out)
    tgemm_kernel<3><<<dim3(4, M1_/128), 256, TG_SMEM>>>(hw, wt + WOFF_FC1, fc1_b, fc1, nullptr, M1_, 512, 128);
    // 7. fc2 GEMM + residual (in place on xres)
    tgemm_kernel<4><<<dim3(1, M1_/128), 256, TG_SMEM>>>(fc1, wt + WOFF_FC2, fc2_b, xres, xres, M1_, 128, 512);
    // 8. patch-merge gather + LN(512): xres -> g_o (rounded, reuse as xm)
    merge_ln_kernel<<<M2_/8, 256>>>(mnw, mnb);
    // 9. merge GEMM -> output
    tgemm_kernel<0><<<dim3(2, M2_/128), 256, TG_SMEM>>>(o, wt + WOFF_MRG, nullptr, out, nullptr, M2_, 256, 512);
}